// round 8
// baseline (speedup 1.0000x reference)
#include <cuda_runtime.h>
#include <cstdint>

// Problem constants
#define BB 4
#define TT 1024
#define DD 1024
#define HH 16
#define DH 64
#define BT (BB*TT)   // 4096

// Scratch (allocation-free: __device__ globals)
__device__ float g_Q[BT*DD];                    // 16 MB
__device__ float g_K[BT*DD];                    // 16 MB
__device__ float g_V[BT*DD];                    // 16 MB
__device__ float g_A[(size_t)BB*HH*TT*TT];      // 256 MB attn matrix
__device__ float g_Xhi[BT*DD];
__device__ float g_Xlo[BT*DD];
__device__ float g_Wthi[3][DD*DD];
__device__ float g_Wtlo[3][DD*DD];
__device__ float g_mx[BB*HH*TT];                // per-row max
__device__ float g_invs[BB*HH*TT];              // per-row 1/sum(exp)

// ---------------------------------------------------------------------------
// Helpers
// ---------------------------------------------------------------------------
__device__ __forceinline__ uint32_t smem_u32(const void* p) {
    uint32_t a;
    asm("{ .reg .u64 t; cvta.to.shared.u64 t, %1; cvt.u32.u64 %0, t; }" : "=r"(a) : "l"(p));
    return a;
}
__device__ __forceinline__ float to_tf32(float v) {
    uint32_t u;
    asm("cvt.rna.tf32.f32 %0, %1;" : "=r"(u) : "f"(v));
    return __uint_as_float(u);
}
__device__ __forceinline__ void cp16(uint32_t dst, const void* src) {
    asm volatile("cp.async.cg.shared.global [%0], [%1], 16;" :: "r"(dst), "l"(src));
}
#define CP_COMMIT() asm volatile("cp.async.commit_group;" ::: "memory")
#define CP_WAIT1()  asm volatile("cp.async.wait_group 1;" ::: "memory")
#define CP_WAIT0()  asm volatile("cp.async.wait_group 0;" ::: "memory")

#define MMA_TF32(d, a, b) \
    asm volatile("mma.sync.aligned.m16n8k8.row.col.f32.tf32.tf32.f32 " \
        "{%0,%1,%2,%3}, {%4,%5,%6,%7}, {%8,%9}, {%0,%1,%2,%3};" \
        : "+f"((d)[0]), "+f"((d)[1]), "+f"((d)[2]), "+f"((d)[3]) \
        : "r"((a)[0]), "r"((a)[1]), "r"((a)[2]), "r"((a)[3]), \
          "r"((b)[0]), "r"((b)[1]))

// ---------------------------------------------------------------------------
// Packed f32x2 helpers (FFMA2)
// ---------------------------------------------------------------------------
__device__ __forceinline__ unsigned long long pack2(float lo, float hi) {
    unsigned long long r;
    asm("mov.b64 %0, {%1, %2};" : "=l"(r) : "f"(lo), "f"(hi));
    return r;
}
__device__ __forceinline__ unsigned long long dup2(float v) {
    unsigned long long r;
    asm("mov.b64 %0, {%1, %1};" : "=l"(r) : "f"(v));
    return r;
}
__device__ __forceinline__ void ffma2(unsigned long long& d,
                                      unsigned long long a,
                                      unsigned long long b) {
    asm("fma.rn.f32x2 %0, %1, %2, %0;" : "+l"(d) : "l"(a), "l"(b));
}
__device__ __forceinline__ float2 unpack2(unsigned long long v) {
    float2 r;
    asm("mov.b64 {%0, %1}, %2;" : "=f"(r.x), "=f"(r.y) : "l"(v));
    return r;
}

// ---------------------------------------------------------------------------
// Prep 1: split X into tf32 hi/lo
// ---------------------------------------------------------------------------
__global__ __launch_bounds__(256) void split_x_kernel(const float* __restrict__ x)
{
    const size_t i4 = ((size_t)blockIdx.x * 256 + threadIdx.x) * 4;
    float4 v = *reinterpret_cast<const float4*>(&x[i4]);
    float4 h, l;
    h.x = to_tf32(v.x); l.x = to_tf32(v.x - h.x);
    h.y = to_tf32(v.y); l.y = to_tf32(v.y - h.y);
    h.z = to_tf32(v.z); l.z = to_tf32(v.z - h.z);
    h.w = to_tf32(v.w); l.w = to_tf32(v.w - h.w);
    *reinterpret_cast<float4*>(&g_Xhi[i4]) = h;
    *reinterpret_cast<float4*>(&g_Xlo[i4]) = l;
}

// ---------------------------------------------------------------------------
// Prep 2: transpose W + tf32 hi/lo split: Wt[n][k] = W[k][n]
// ---------------------------------------------------------------------------
__global__ void wtrans_kernel(const float* __restrict__ W, int widx)
{
    __shared__ float s[32][33];
    const int tx = threadIdx.x;
    const int ty = threadIdx.y;
    const int k0 = blockIdx.x * 32;
    const int n0 = blockIdx.y * 32;

    #pragma unroll
    for (int i = 0; i < 4; i++)
        s[ty + i * 8][tx] = W[(size_t)(k0 + ty + i * 8) * DD + n0 + tx];
    __syncthreads();

    float* hi = g_Wthi[widx];
    float* lo = g_Wtlo[widx];
    #pragma unroll
    for (int i = 0; i < 4; i++) {
        float v = s[tx][ty + i * 8];
        float h = to_tf32(v);
        hi[(size_t)(n0 + ty + i * 8) * DD + k0 + tx] = h;
        lo[(size_t)(n0 + ty + i * 8) * DD + k0 + tx] = to_tf32(v - h);
    }
}

// ---------------------------------------------------------------------------
// Kernel 1: projection GEMM via mma.sync m16n8k8 tf32, 3xTF32 hi/lo split.
// ---------------------------------------------------------------------------
#define ROWPAD 36
#define A_F    (128 * ROWPAD)
#define B_F    (128 * 32)
#define STG_F  (2 * A_F + 2 * B_F)
#define PROJ_SMEM (2 * STG_F * 4)
#define NCHUNK 32

__global__ __launch_bounds__(256, 1) void proj_mma_kernel(
    const float* __restrict__ Ahi_g, const float* __restrict__ Alo_g,
    const float* __restrict__ Bhi_g, const float* __restrict__ Blo_g,
    const float* __restrict__ bias, float* __restrict__ C)
{
    extern __shared__ float sm[];
    const uint32_t sbase = smem_u32(sm);

    const int tid = threadIdx.x;
    const int wid = tid >> 5;
    const int lane = tid & 31;
    const int lq  = lane >> 2;
    const int lr  = lane & 3;

    const int row0 = blockIdx.y * 128;
    const int col0 = blockIdx.x * 128;

    const int m0 = (wid >> 1) * 32;
    const int n0 = (wid & 1) * 64;

    auto load_chunk = [&](int kc, int stage) {
        const int k0 = kc * 32;
        const uint32_t st = sbase + (uint32_t)stage * STG_F * 4;
        #pragma unroll
        for (int i = 0; i < 4; i++) {
            const int c = tid + i * 256;
            const int r = c >> 3;
            const int o = c & 7;
            const uint32_t soA = (uint32_t)(r * ROWPAD * 4 + o * 16);
            const uint32_t soB = (uint32_t)(r * 128 + ((o ^ (r & 7)) * 16));
            const size_t ga = (size_t)(row0 + r) * DD + k0 + o * 4;
            const size_t gb = (size_t)(col0 + r) * DD + k0 + o * 4;
            cp16(st + 0 * A_F * 4 + soA, &Ahi_g[ga]);
            cp16(st + 1 * A_F * 4 + soA, &Alo_g[ga]);
            cp16(st + (2 * A_F + 0 * B_F) * 4 + soB, &Bhi_g[gb]);
            cp16(st + (2 * A_F + 1 * B_F) * 4 + soB, &Blo_g[gb]);
        }
        CP_COMMIT();
    };

    float acc[2][8][4];
    #pragma unroll
    for (int mt = 0; mt < 2; mt++)
        #pragma unroll
        for (int nt = 0; nt < 8; nt++)
            #pragma unroll
            for (int r = 0; r < 4; r++)
                acc[mt][nt][r] = 0.f;

    load_chunk(0, 0);
    load_chunk(1, 1);

    for (int kc = 0; kc < NCHUNK; kc++) {
        if (kc == NCHUNK - 1) { CP_WAIT0(); } else { CP_WAIT1(); }
        __syncthreads();

        const float* st = sm + (kc & 1) * STG_F;
        const float* Ah = st;
        const float* Al = st + A_F;
        const float* Bh = st + 2 * A_F;
        const float* Bl = st + 2 * A_F + B_F;

        #pragma unroll
        for (int s = 0; s < 4; s++) {
            const int k = s * 8;
            uint32_t ahi[2][4], alo[2][4];
            #pragma unroll
            for (int mt = 0; mt < 2; mt++) {
                const int r = m0 + mt * 16 + lq;
                ahi[mt][0] = __float_as_uint(Ah[r * ROWPAD + k + lr]);
                ahi[mt][1] = __float_as_uint(Ah[(r + 8) * ROWPAD + k + lr]);
                ahi[mt][2] = __float_as_uint(Ah[r * ROWPAD + k + 4 + lr]);
                ahi[mt][3] = __float_as_uint(Ah[(r + 8) * ROWPAD + k + 4 + lr]);
                alo[mt][0] = __float_as_uint(Al[r * ROWPAD + k + lr]);
                alo[mt][1] = __float_as_uint(Al[(r + 8) * ROWPAD + k + lr]);
                alo[mt][2] = __float_as_uint(Al[r * ROWPAD + k + 4 + lr]);
                alo[mt][3] = __float_as_uint(Al[(r + 8) * ROWPAD + k + 4 + lr]);
            }
            #pragma unroll
            for (int nt = 0; nt < 8; nt++) {
                const int n = n0 + nt * 8 + lq;
                const int nb = n * 32;
                const int x0 = ((2 * s) ^ (n & 7)) << 2;
                const int x1 = ((2 * s + 1) ^ (n & 7)) << 2;
                uint32_t bhi[2], blo[2];
                bhi[0] = __float_as_uint(Bh[nb + x0 + lr]);
                bhi[1] = __float_as_uint(Bh[nb + x1 + lr]);
                blo[0] = __float_as_uint(Bl[nb + x0 + lr]);
                blo[1] = __float_as_uint(Bl[nb + x1 + lr]);
                MMA_TF32(acc[0][nt], ahi[0], bhi);
                MMA_TF32(acc[1][nt], ahi[1], bhi);
                MMA_TF32(acc[0][nt], ahi[0], blo);
                MMA_TF32(acc[1][nt], ahi[1], blo);
                MMA_TF32(acc[0][nt], alo[0], bhi);
                MMA_TF32(acc[1][nt], alo[1], bhi);
            }
        }
        __syncthreads();
        if (kc + 2 < NCHUNK) load_chunk(kc + 2, kc & 1);
    }

    #pragma unroll
    for (int mt = 0; mt < 2; mt++) {
        const int rm = row0 + m0 + mt * 16 + lq;
        #pragma unroll
        for (int nt = 0; nt < 8; nt++) {
            const int cn = col0 + n0 + nt * 8 + 2 * lr;
            const float2 bv = *reinterpret_cast<const float2*>(&bias[cn]);
            float2 v0 = make_float2(acc[mt][nt][0] + bv.x, acc[mt][nt][1] + bv.y);
            float2 v1 = make_float2(acc[mt][nt][2] + bv.x, acc[mt][nt][3] + bv.y);
            *reinterpret_cast<float2*>(&C[(size_t)rm * DD + cn])       = v0;
            *reinterpret_cast<float2*>(&C[(size_t)(rm + 8) * DD + cn]) = v1;
        }
    }
}

// ---------------------------------------------------------------------------
// Kernel 2: attn strip kernel with fused online softmax stats.
// Block = (t-tile 128 rows) x (bh).  K tile staged once; V streamed over 8
// s-chunks (cp.async double-buffered).  Writes scaled A tiles + g_mx/g_invs.
// smem: Ks 64x128 (32KB) + Vs 2x64x128 (64KB) = 96KB
// Each 64x128 tile = 64 rows x 32 sixteen-byte chunks = 2048 cp16.
// ---------------------------------------------------------------------------
#define ATTN_SMEM ((64*128 + 2*64*128) * 4)   // 98304

__global__ __launch_bounds__(256) void attn_kernel(const float* __restrict__ temperature)
{
    extern __shared__ float smf[];
    float* Ks = smf;                  // [d][t]  64x128
    float* Vs = smf + 64 * 128;       // [2][d][s] 2x64x128

    const int tid = threadIdx.x;
    const int tx = tid & 15;
    const int ty = tid >> 4;
    const int t0 = blockIdx.x * 128;
    const int bh = blockIdx.y;
    const int b  = bh >> 4;
    const int h  = bh & 15;

    const uint32_t sbase = smem_u32(smf);
    const float* Kh = g_K + (size_t)b * TT * DD + (size_t)(h * DH) * DD;
    const float* Vh = g_V + (size_t)b * TT * DD + (size_t)(h * DH) * DD;

    // load K tile + first two V chunks (each: 64 rows x 512B = 2048 cp16)
    {
        #pragma unroll
        for (int i = 0; i < 8; i++) {
            const int f = i * 256 + tid;       // 0..2047
            const int d = f >> 5;              // 0..63
            const int c = (f & 31) * 16;       // 0..496 byte offset within row
            cp16(sbase + (uint32_t)(d * 512 + c), &Kh[(size_t)d * DD + t0 + (c >> 2)]);
        }
        #pragma unroll
        for (int i = 0; i < 8; i++) {
            const int f = i * 256 + tid;
            const int d = f >> 5;
            const int c = (f & 31) * 16;
            cp16(sbase + (uint32_t)(64 * 512 + d * 512 + c), &Vh[(size_t)d * DD + 0 + (c >> 2)]);
        }
        CP_COMMIT();
        #pragma unroll
        for (int i = 0; i < 8; i++) {
            const int f = i * 256 + tid;
            const int d = f >> 5;
            const int c = (f & 31) * 16;
            cp16(sbase + (uint32_t)(128 * 512 + d * 512 + c), &Vh[(size_t)d * DD + 128 + (c >> 2)]);
        }
        CP_COMMIT();
    }

    const float tmp = temperature[h];
    float m_run[8], s_run[8];
    #pragma unroll
    for (int r = 0; r < 8; r++) { m_run[r] = -3.402823466e+38f; s_run[r] = 0.f; }

    for (int sc = 0; sc < 8; sc++) {
        if (sc == 7) { CP_WAIT0(); } else { CP_WAIT1(); }
        __syncthreads();

        const float* Vc = Vs + (sc & 1) * 64 * 128;

        unsigned long long acc[4][8] = {};
        #pragma unroll 8
        for (int d = 0; d < 64; d++) {
            float4 a0 = *reinterpret_cast<const float4*>(&Ks[d * 128 + ty * 8]);
            float4 a1 = *reinterpret_cast<const float4*>(&Ks[d * 128 + ty * 8 + 4]);
            float4 b0 = *reinterpret_cast<const float4*>(&Vc[d * 128 + tx * 8]);
            float4 b1 = *reinterpret_cast<const float4*>(&Vc[d * 128 + tx * 8 + 4]);
            unsigned long long a2[4] = {pack2(a0.x, a0.y), pack2(a0.z, a0.w),
                                        pack2(a1.x, a1.y), pack2(a1.z, a1.w)};
            unsigned long long bb[8] = {dup2(b0.x), dup2(b0.y), dup2(b0.z), dup2(b0.w),
                                        dup2(b1.x), dup2(b1.y), dup2(b1.z), dup2(b1.w)};
            #pragma unroll
            for (int ip = 0; ip < 4; ip++)
                #pragma unroll
                for (int j = 0; j < 8; j++)
                    ffma2(acc[ip][j], a2[ip], bb[j]);
        }
        __syncthreads();
        // prefetch V chunk sc+2 into the buffer we just finished reading
        if (sc + 2 < 8) {
            #pragma unroll
            for (int i = 0; i < 8; i++) {
                const int f = i * 256 + tid;
                const int d = f >> 5;
                const int c = (f & 31) * 16;
                cp16(sbase + (uint32_t)((64 + (sc & 1) * 64) * 512 + d * 512 + c),
                     &Vh[(size_t)d * DD + (sc + 2) * 128 + (c >> 2)]);
            }
            CP_COMMIT();
        }

        // scale, write tile, update online stats
        float* Abase = g_A + ((size_t)bh * TT + t0) * TT + sc * 128;
        #pragma unroll
        for (int ip = 0; ip < 4; ip++) {
            float r0[8], r1[8];
            #pragma unroll
            for (int j = 0; j < 8; j++) {
                float2 v = unpack2(acc[ip][j]);
                r0[j] = v.x * tmp;
                r1[j] = v.y * tmp;
            }
            float* p0 = &Abase[(size_t)(ty * 8 + 2 * ip) * TT + tx * 8];
            float* p1 = p0 + TT;
            *reinterpret_cast<float4*>(p0)     = make_float4(r0[0], r0[1], r0[2], r0[3]);
            *reinterpret_cast<float4*>(p0 + 4) = make_float4(r0[4], r0[5], r0[6], r0[7]);
            *reinterpret_cast<float4*>(p1)     = make_float4(r1[0], r1[1], r1[2], r1[3]);
            *reinterpret_cast<float4*>(p1 + 4) = make_float4(r1[4], r1[5], r1[6], r1[7]);

            #pragma unroll
            for (int half = 0; half < 2; half++) {
                const float* rv = half ? r1 : r0;
                float tmax = rv[0];
                #pragma unroll
                for (int j = 1; j < 8; j++) tmax = fmaxf(tmax, rv[j]);
                #pragma unroll
                for (int off = 8; off > 0; off >>= 1)
                    tmax = fmaxf(tmax, __shfl_xor_sync(0xffffffffu, tmax, off));
                const int rr = 2 * ip + half;
                const float mo = m_run[rr];
                const float mn = fmaxf(mo, tmax);
                float ps = 0.f;
                #pragma unroll
                for (int j = 0; j < 8; j++) ps += __expf(rv[j] - mn);
                s_run[rr] = s_run[rr] * __expf(mo - mn) + ps;
                m_run[rr] = mn;
            }
        }
    }

    // final row stats: reduce partial sums across the 16-lane tx group
    #pragma unroll
    for (int rr = 0; rr < 8; rr++) {
        float ssum = s_run[rr];
        #pragma unroll
        for (int off = 8; off > 0; off >>= 1)
            ssum += __shfl_xor_sync(0xffffffffu, ssum, off);
        if (tx == 0) {
            const size_t row = (size_t)bh * TT + t0 + ty * 8 + rr;
            g_mx[row]   = m_run[rr];
            g_invs[row] = 1.0f / ssum;
        }
    }
}

// ---------------------------------------------------------------------------
// Kernel 3: out rows [h*64,h*64+64) = (Qh * invs) @ exp(A - mx)   (FFMA2)
// ---------------------------------------------------------------------------
__global__ __launch_bounds__(256) void out_kernel(float* __restrict__ out)
{
    __shared__ float Qs[32][68];
    __shared__ float Ps[32][128];

    const int tid = threadIdx.x;
    const int tx = tid & 15;
    const int ty = tid >> 4;
    const int bh = blockIdx.z;
    const int b  = bh >> 4;
    const int h  = bh & 15;
    const int s0 = blockIdx.x * 128;

    const float* Qh   = g_Q + (size_t)b * TT * DD + (size_t)(h * DH) * DD;
    const float* Abh  = g_A + (size_t)bh * TT * TT;
    const float* mxp  = g_mx + (size_t)bh * TT;
    const float* invp = g_invs + (size_t)bh * TT;

    unsigned long long acc[2][8] = {};

    for (int k0 = 0; k0 < TT; k0 += 32) {
        #pragma unroll
        for (int i = 0; i < 2; i++) {
            const int idx = i * 256 + tid;
            const int r  = idx >> 3;
            const int c4 = (idx & 7) * 4;
            float4 q  = *reinterpret_cast<const float4*>(&Qh[(size_t)r * DD + k0 + c4]);
            float4 iv = *reinterpret_cast<const float4*>(&invp[k0 + c4]);
            Qs[c4 + 0][r] = q.x * iv.x; Qs[c4 + 1][r] = q.y * iv.y;
            Qs[c4 + 2][r] = q.z * iv.z; Qs[c4 + 3][r] = q.w * iv.w;
        }
        #pragma unroll
        for (int i = 0; i < 4; i++) {
            const int idx = i * 256 + tid;
            const int r  = idx >> 5;
            const int c4 = (idx & 31) * 4;
            float4 a = *reinterpret_cast<const float4*>(&Abh[(size_t)(k0 + r) * TT + s0 + c4]);
            const float m = mxp[k0 + r];
            float4 p;
            p.x = __expf(a.x - m); p.y = __expf(a.y - m);
            p.z = __expf(a.z - m); p.w = __expf(a.w - m);
            *reinterpret_cast<float4*>(&Ps[r][c4]) = p;
        }
        __syncthreads();

        #pragma unroll
        for (int k = 0; k < 32; k++) {
            float4 a  = *reinterpret_cast<const float4*>(&Qs[k][ty * 4]);
            float4 b0 = *reinterpret_cast<const float4*>(&Ps[k][tx * 8]);
            float4 b1 = *reinterpret_cast<const float4*>(&Ps[k][tx * 8 + 4]);
            unsigned long long a2[2] = {pack2(a.x, a.y), pack2(a.z, a.w)};
            unsigned long long bb[8] = {dup2(b0.x), dup2(b0.y), dup2(b0.z), dup2(b0.w),
                                        dup2(b1.x), dup2(b1.y), dup2(b1.z), dup2(b1.w)};
            #pragma unroll
            for (int ip = 0; ip < 2; ip++)
                #pragma unroll
                for (int j = 0; j < 8; j++)
                    ffma2(acc[ip][j], a2[ip], bb[j]);
        }
        __syncthreads();
    }

    float* orow = out + (size_t)b * TT * DD + (size_t)(h * DH) * DD;
    #pragma unroll
    for (int ip = 0; ip < 2; ip++) {
        float r0[8], r1[8];
        #pragma unroll
        for (int j = 0; j < 8; j++) {
            float2 v = unpack2(acc[ip][j]);
            r0[j] = v.x;
            r1[j] = v.y;
        }
        float* p0 = &orow[(size_t)(ty * 4 + 2 * ip) * DD + s0 + tx * 8];
        float* p1 = p0 + DD;
        *reinterpret_cast<float4*>(p0)     = make_float4(r0[0], r0[1], r0[2], r0[3]);
        *reinterpret_cast<float4*>(p0 + 4) = make_float4(r0[4], r0[5], r0[6], r0[7]);
        *reinterpret_cast<float4*>(p1)     = make_float4(r1[0], r1[1], r1[2], r1[3]);
        *reinterpret_cast<float4*>(p1 + 4) = make_float4(r1[4], r1[5], r1[6], r1[7]);
    }
}

// ---------------------------------------------------------------------------
extern "C" void kernel_launch(void* const* d_in, const int* in_sizes, int n_in,
                              void* d_out, int out_size)
{
    const float* x    = (const float*)d_in[0];
    const float* Wq   = (const float*)d_in[1];
    const float* bq   = (const float*)d_in[2];
    const float* Wk   = (const float*)d_in[3];
    const float* bk   = (const float*)d_in[4];
    const float* Wv   = (const float*)d_in[5];
    const float* bv   = (const float*)d_in[6];
    const float* temp = (const float*)d_in[7];
    float* out = (float*)d_out;

    static float* Qp = nullptr;
    static float *Kp, *Vp, *Xhi, *Xlo, *Wthi, *Wtlo;
    if (!Qp) {
        cudaGetSymbolAddress((void**)&Qp, g_Q);
        cudaGetSymbolAddress((void**)&Kp, g_K);
        cudaGetSymbolAddress((void**)&Vp, g_V);
        cudaGetSymbolAddress((void**)&Xhi, g_Xhi);
        cudaGetSymbolAddress((void**)&Xlo, g_Xlo);
        cudaGetSymbolAddress((void**)&Wthi, g_Wthi);
        cudaGetSymbolAddress((void**)&Wtlo, g_Wtlo);
        cudaFuncSetAttribute(proj_mma_kernel,
                             cudaFuncAttributeMaxDynamicSharedMemorySize, PROJ_SMEM);
        cudaFuncSetAttribute(attn_kernel,
                             cudaFuncAttributeMaxDynamicSharedMemorySize, ATTN_SMEM);
    }

    split_x_kernel<<<BT * DD / 1024, 256>>>(x);
    {
        dim3 tg(32, 32);
        dim3 tb(32, 8);
        wtrans_kernel<<<tg, tb>>>(Wq, 0);
        wtrans_kernel<<<tg, tb>>>(Wk, 1);
        wtrans_kernel<<<tg, tb>>>(Wv, 2);
    }

    dim3 pgrid(DD / 128, BT / 128);   // 8 x 32
    proj_mma_kernel<<<pgrid, 256, PROJ_SMEM>>>(Xhi, Xlo, Wthi + 0 * (size_t)DD * DD, Wtlo + 0 * (size_t)DD * DD, bq, Qp);
    proj_mma_kernel<<<pgrid, 256, PROJ_SMEM>>>(Xhi, Xlo, Wthi + 1 * (size_t)DD * DD, Wtlo + 1 * (size_t)DD * DD, bk, Kp);
    proj_mma_kernel<<<pgrid, 256, PROJ_SMEM>>>(Xhi, Xlo, Wthi + 2 * (size_t)DD * DD, Wtlo + 2 * (size_t)DD * DD, bv, Vp);

    dim3 agrid(TT / 128, BB * HH);    // 8 x 64 strip blocks
    attn_kernel<<<agrid, 256, ATTN_SMEM>>>(temp);

    dim3 ogrid(TT / 128, 1, BB * HH); // 8 x 1 x 64
    out_kernel<<<ogrid, 256>>>(out);
}

// round 9
// speedup vs baseline: 1.6702x; 1.6702x over previous
#include <cuda_runtime.h>
#include <cstdint>

// Problem constants
#define BB 4
#define TT 1024
#define DD 1024
#define HH 16
#define DH 64
#define BT (BB*TT)   // 4096

// Scratch (allocation-free: __device__ globals)
__device__ float g_Q[BT*DD];                    // 16 MB
__device__ float g_K[BT*DD];                    // 16 MB
__device__ float g_V[BT*DD];                    // 16 MB
__device__ float g_A[(size_t)BB*HH*TT*TT];      // 256 MB attn matrix
__device__ float g_Xhi[BT*DD];
__device__ float g_Xlo[BT*DD];
__device__ float g_Wthi[3][DD*DD];
__device__ float g_Wtlo[3][DD*DD];
__device__ float g_mx[BB*HH*TT];                // per-row max
__device__ float g_invs[BB*HH*TT];              // per-row 1/sum(exp)

// ---------------------------------------------------------------------------
// Helpers
// ---------------------------------------------------------------------------
__device__ __forceinline__ uint32_t smem_u32(const void* p) {
    uint32_t a;
    asm("{ .reg .u64 t; cvta.to.shared.u64 t, %1; cvt.u32.u64 %0, t; }" : "=r"(a) : "l"(p));
    return a;
}
__device__ __forceinline__ float to_tf32(float v) {
    uint32_t u;
    asm("cvt.rna.tf32.f32 %0, %1;" : "=r"(u) : "f"(v));
    return __uint_as_float(u);
}
__device__ __forceinline__ void cp16(uint32_t dst, const void* src) {
    asm volatile("cp.async.cg.shared.global [%0], [%1], 16;" :: "r"(dst), "l"(src));
}
#define CP_COMMIT() asm volatile("cp.async.commit_group;" ::: "memory")
#define CP_WAIT1()  asm volatile("cp.async.wait_group 1;" ::: "memory")
#define CP_WAIT0()  asm volatile("cp.async.wait_group 0;" ::: "memory")

#define MMA_TF32(d, a, b) \
    asm volatile("mma.sync.aligned.m16n8k8.row.col.f32.tf32.tf32.f32 " \
        "{%0,%1,%2,%3}, {%4,%5,%6,%7}, {%8,%9}, {%0,%1,%2,%3};" \
        : "+f"((d)[0]), "+f"((d)[1]), "+f"((d)[2]), "+f"((d)[3]) \
        : "r"((a)[0]), "r"((a)[1]), "r"((a)[2]), "r"((a)[3]), \
          "r"((b)[0]), "r"((b)[1]))

// ---------------------------------------------------------------------------
// Packed f32x2 helpers (FFMA2)
// ---------------------------------------------------------------------------
__device__ __forceinline__ unsigned long long pack2(float lo, float hi) {
    unsigned long long r;
    asm("mov.b64 %0, {%1, %2};" : "=l"(r) : "f"(lo), "f"(hi));
    return r;
}
__device__ __forceinline__ unsigned long long dup2(float v) {
    unsigned long long r;
    asm("mov.b64 %0, {%1, %1};" : "=l"(r) : "f"(v));
    return r;
}
__device__ __forceinline__ void ffma2(unsigned long long& d,
                                      unsigned long long a,
                                      unsigned long long b) {
    asm("fma.rn.f32x2 %0, %1, %2, %0;" : "+l"(d) : "l"(a), "l"(b));
}
__device__ __forceinline__ float2 unpack2(unsigned long long v) {
    float2 r;
    asm("mov.b64 {%0, %1}, %2;" : "=f"(r.x), "=f"(r.y) : "l"(v));
    return r;
}

// ---------------------------------------------------------------------------
// Prep 1: split X into tf32 hi/lo
// ---------------------------------------------------------------------------
__global__ __launch_bounds__(256) void split_x_kernel(const float* __restrict__ x)
{
    const size_t i4 = ((size_t)blockIdx.x * 256 + threadIdx.x) * 4;
    float4 v = *reinterpret_cast<const float4*>(&x[i4]);
    float4 h, l;
    h.x = to_tf32(v.x); l.x = to_tf32(v.x - h.x);
    h.y = to_tf32(v.y); l.y = to_tf32(v.y - h.y);
    h.z = to_tf32(v.z); l.z = to_tf32(v.z - h.z);
    h.w = to_tf32(v.w); l.w = to_tf32(v.w - h.w);
    *reinterpret_cast<float4*>(&g_Xhi[i4]) = h;
    *reinterpret_cast<float4*>(&g_Xlo[i4]) = l;
}

// ---------------------------------------------------------------------------
// Prep 2: transpose W + tf32 hi/lo split: Wt[n][k] = W[k][n]
// ---------------------------------------------------------------------------
__global__ void wtrans_kernel(const float* __restrict__ W, int widx)
{
    __shared__ float s[32][33];
    const int tx = threadIdx.x;
    const int ty = threadIdx.y;
    const int k0 = blockIdx.x * 32;
    const int n0 = blockIdx.y * 32;

    #pragma unroll
    for (int i = 0; i < 4; i++)
        s[ty + i * 8][tx] = W[(size_t)(k0 + ty + i * 8) * DD + n0 + tx];
    __syncthreads();

    float* hi = g_Wthi[widx];
    float* lo = g_Wtlo[widx];
    #pragma unroll
    for (int i = 0; i < 4; i++) {
        float v = s[tx][ty + i * 8];
        float h = to_tf32(v);
        hi[(size_t)(n0 + ty + i * 8) * DD + k0 + tx] = h;
        lo[(size_t)(n0 + ty + i * 8) * DD + k0 + tx] = to_tf32(v - h);
    }
}

// ---------------------------------------------------------------------------
// Kernel 1: projection GEMM via mma.sync m16n8k8 tf32, 3xTF32 hi/lo split.
// ---------------------------------------------------------------------------
#define ROWPAD 36
#define A_F    (128 * ROWPAD)
#define B_F    (128 * 32)
#define STG_F  (2 * A_F + 2 * B_F)
#define PROJ_SMEM (2 * STG_F * 4)
#define NCHUNK 32

__global__ __launch_bounds__(256, 1) void proj_mma_kernel(
    const float* __restrict__ Ahi_g, const float* __restrict__ Alo_g,
    const float* __restrict__ Bhi_g, const float* __restrict__ Blo_g,
    const float* __restrict__ bias, float* __restrict__ C)
{
    extern __shared__ float sm[];
    const uint32_t sbase = smem_u32(sm);

    const int tid = threadIdx.x;
    const int wid = tid >> 5;
    const int lane = tid & 31;
    const int lq  = lane >> 2;
    const int lr  = lane & 3;

    const int row0 = blockIdx.y * 128;
    const int col0 = blockIdx.x * 128;

    const int m0 = (wid >> 1) * 32;
    const int n0 = (wid & 1) * 64;

    auto load_chunk = [&](int kc, int stage) {
        const int k0 = kc * 32;
        const uint32_t st = sbase + (uint32_t)stage * STG_F * 4;
        #pragma unroll
        for (int i = 0; i < 4; i++) {
            const int c = tid + i * 256;
            const int r = c >> 3;
            const int o = c & 7;
            const uint32_t soA = (uint32_t)(r * ROWPAD * 4 + o * 16);
            const uint32_t soB = (uint32_t)(r * 128 + ((o ^ (r & 7)) * 16));
            const size_t ga = (size_t)(row0 + r) * DD + k0 + o * 4;
            const size_t gb = (size_t)(col0 + r) * DD + k0 + o * 4;
            cp16(st + 0 * A_F * 4 + soA, &Ahi_g[ga]);
            cp16(st + 1 * A_F * 4 + soA, &Alo_g[ga]);
            cp16(st + (2 * A_F + 0 * B_F) * 4 + soB, &Bhi_g[gb]);
            cp16(st + (2 * A_F + 1 * B_F) * 4 + soB, &Blo_g[gb]);
        }
        CP_COMMIT();
    };

    float acc[2][8][4];
    #pragma unroll
    for (int mt = 0; mt < 2; mt++)
        #pragma unroll
        for (int nt = 0; nt < 8; nt++)
            #pragma unroll
            for (int r = 0; r < 4; r++)
                acc[mt][nt][r] = 0.f;

    load_chunk(0, 0);
    load_chunk(1, 1);

    for (int kc = 0; kc < NCHUNK; kc++) {
        if (kc == NCHUNK - 1) { CP_WAIT0(); } else { CP_WAIT1(); }
        __syncthreads();

        const float* st = sm + (kc & 1) * STG_F;
        const float* Ah = st;
        const float* Al = st + A_F;
        const float* Bh = st + 2 * A_F;
        const float* Bl = st + 2 * A_F + B_F;

        #pragma unroll
        for (int s = 0; s < 4; s++) {
            const int k = s * 8;
            uint32_t ahi[2][4], alo[2][4];
            #pragma unroll
            for (int mt = 0; mt < 2; mt++) {
                const int r = m0 + mt * 16 + lq;
                ahi[mt][0] = __float_as_uint(Ah[r * ROWPAD + k + lr]);
                ahi[mt][1] = __float_as_uint(Ah[(r + 8) * ROWPAD + k + lr]);
                ahi[mt][2] = __float_as_uint(Ah[r * ROWPAD + k + 4 + lr]);
                ahi[mt][3] = __float_as_uint(Ah[(r + 8) * ROWPAD + k + 4 + lr]);
                alo[mt][0] = __float_as_uint(Al[r * ROWPAD + k + lr]);
                alo[mt][1] = __float_as_uint(Al[(r + 8) * ROWPAD + k + lr]);
                alo[mt][2] = __float_as_uint(Al[r * ROWPAD + k + 4 + lr]);
                alo[mt][3] = __float_as_uint(Al[(r + 8) * ROWPAD + k + 4 + lr]);
            }
            #pragma unroll
            for (int nt = 0; nt < 8; nt++) {
                const int n = n0 + nt * 8 + lq;
                const int nb = n * 32;
                const int x0 = ((2 * s) ^ (n & 7)) << 2;
                const int x1 = ((2 * s + 1) ^ (n & 7)) << 2;
                uint32_t bhi[2], blo[2];
                bhi[0] = __float_as_uint(Bh[nb + x0 + lr]);
                bhi[1] = __float_as_uint(Bh[nb + x1 + lr]);
                blo[0] = __float_as_uint(Bl[nb + x0 + lr]);
                blo[1] = __float_as_uint(Bl[nb + x1 + lr]);
                MMA_TF32(acc[0][nt], ahi[0], bhi);
                MMA_TF32(acc[1][nt], ahi[1], bhi);
                MMA_TF32(acc[0][nt], ahi[0], blo);
                MMA_TF32(acc[1][nt], ahi[1], blo);
                MMA_TF32(acc[0][nt], alo[0], bhi);
                MMA_TF32(acc[1][nt], alo[1], bhi);
            }
        }
        __syncthreads();
        if (kc + 2 < NCHUNK) load_chunk(kc + 2, kc & 1);
    }

    #pragma unroll
    for (int mt = 0; mt < 2; mt++) {
        const int rm = row0 + m0 + mt * 16 + lq;
        #pragma unroll
        for (int nt = 0; nt < 8; nt++) {
            const int cn = col0 + n0 + nt * 8 + 2 * lr;
            const float2 bv = *reinterpret_cast<const float2*>(&bias[cn]);
            float2 v0 = make_float2(acc[mt][nt][0] + bv.x, acc[mt][nt][1] + bv.y);
            float2 v1 = make_float2(acc[mt][nt][2] + bv.x, acc[mt][nt][3] + bv.y);
            *reinterpret_cast<float2*>(&C[(size_t)rm * DD + cn])       = v0;
            *reinterpret_cast<float2*>(&C[(size_t)(rm + 8) * DD + cn]) = v1;
        }
    }
}

// ---------------------------------------------------------------------------
// Kernel 2: attn[b,h,t,s] = temp[h] * sum_d Kh[d,t] * Vh[d,s]   (FFMA2)
// (exact R6 version — measured good)
// ---------------------------------------------------------------------------
__global__ __launch_bounds__(256) void attn_kernel(const float* __restrict__ temperature)
{
    extern __shared__ float smf[];
    float (*Ks)[128] = reinterpret_cast<float (*)[128]>(smf);
    float (*Vs)[128] = reinterpret_cast<float (*)[128]>(smf + 64*128);

    const int tid = threadIdx.x;
    const int tx = tid & 15;
    const int ty = tid >> 4;
    const int bh = blockIdx.z;
    const int b  = bh >> 4;
    const int h  = bh & 15;
    const int t0 = blockIdx.y * 128;
    const int s0 = blockIdx.x * 128;

    const float* Kh = g_K + (size_t)b * TT * DD + (size_t)(h * DH) * DD;
    const float* Vh = g_V + (size_t)b * TT * DD + (size_t)(h * DH) * DD;

    #pragma unroll
    for (int i = 0; i < 8; i++) {
        const int idx = i * 256 + tid;
        const int d  = idx >> 5;
        const int c4 = (idx & 31) * 4;
        *reinterpret_cast<float4*>(&Ks[d][c4]) =
            *reinterpret_cast<const float4*>(&Kh[(size_t)d * DD + t0 + c4]);
        *reinterpret_cast<float4*>(&Vs[d][c4]) =
            *reinterpret_cast<const float4*>(&Vh[(size_t)d * DD + s0 + c4]);
    }
    __syncthreads();

    unsigned long long acc[4][8] = {};

    #pragma unroll 8
    for (int d = 0; d < 64; d++) {
        float4 a0 = *reinterpret_cast<const float4*>(&Ks[d][ty * 8]);
        float4 a1 = *reinterpret_cast<const float4*>(&Ks[d][ty * 8 + 4]);
        float4 b0 = *reinterpret_cast<const float4*>(&Vs[d][tx * 8]);
        float4 b1 = *reinterpret_cast<const float4*>(&Vs[d][tx * 8 + 4]);
        unsigned long long a2[4] = {pack2(a0.x, a0.y), pack2(a0.z, a0.w),
                                    pack2(a1.x, a1.y), pack2(a1.z, a1.w)};
        unsigned long long bb[8] = {dup2(b0.x), dup2(b0.y), dup2(b0.z), dup2(b0.w),
                                    dup2(b1.x), dup2(b1.y), dup2(b1.z), dup2(b1.w)};
        #pragma unroll
        for (int ip = 0; ip < 4; ip++)
            #pragma unroll
            for (int j = 0; j < 8; j++)
                ffma2(acc[ip][j], a2[ip], bb[j]);
    }

    const float tmp = temperature[h];
    float* Abase = g_A + ((size_t)bh * TT + t0) * TT + s0;
    #pragma unroll
    for (int ip = 0; ip < 4; ip++) {
        float r0[8], r1[8];
        #pragma unroll
        for (int j = 0; j < 8; j++) {
            float2 v = unpack2(acc[ip][j]);
            r0[j] = v.x * tmp;
            r1[j] = v.y * tmp;
        }
        float* p0 = &Abase[(size_t)(ty * 8 + 2 * ip) * TT + tx * 8];
        float* p1 = p0 + TT;
        *reinterpret_cast<float4*>(p0)     = make_float4(r0[0], r0[1], r0[2], r0[3]);
        *reinterpret_cast<float4*>(p0 + 4) = make_float4(r0[4], r0[5], r0[6], r0[7]);
        *reinterpret_cast<float4*>(p1)     = make_float4(r1[0], r1[1], r1[2], r1[3]);
        *reinterpret_cast<float4*>(p1 + 4) = make_float4(r1[4], r1[5], r1[6], r1[7]);
    }
}

// ---------------------------------------------------------------------------
// Kernel 3: per-row max + 1/sum(exp) stats (read-only over g_A).
// ---------------------------------------------------------------------------
__global__ __launch_bounds__(256) void rowstat_kernel()
{
    const int warp_in_block = threadIdx.x >> 5;
    const int lane = threadIdx.x & 31;
    const size_t row = (size_t)blockIdx.x * 8 + warp_in_block;

    const float* rp = g_A + row * TT;

    float vals[32];
    float mx = -3.402823466e+38f;
    #pragma unroll
    for (int i = 0; i < 8; i++) {
        float4 v = *reinterpret_cast<const float4*>(&rp[(i * 32 + lane) * 4]);
        vals[i * 4 + 0] = v.x; vals[i * 4 + 1] = v.y;
        vals[i * 4 + 2] = v.z; vals[i * 4 + 3] = v.w;
        mx = fmaxf(mx, fmaxf(fmaxf(v.x, v.y), fmaxf(v.z, v.w)));
    }
    #pragma unroll
    for (int off = 16; off > 0; off >>= 1)
        mx = fmaxf(mx, __shfl_xor_sync(0xffffffffu, mx, off));

    float sum = 0.f;
    #pragma unroll
    for (int i = 0; i < 32; i++)
        sum += __expf(vals[i] - mx);
    #pragma unroll
    for (int off = 16; off > 0; off >>= 1)
        sum += __shfl_xor_sync(0xffffffffu, sum, off);

    if (lane == 0) {
        g_mx[row]   = mx;
        g_invs[row] = 1.0f / sum;
    }
}

// ---------------------------------------------------------------------------
// Kernel 4: out rows = (Qh * invs) @ exp(A - mx) via mma.sync tf32 3x.
// Tile 64(d) x 128(s), BK=32 over t.  256 threads, 8 warps (2x4, 32x32 each).
// Q staged pad-36 (conflict-free A frags); P staged TRANSPOSED pad-33
// (2-way B frags).  exp + hi/lo split fused into staging; invs folded into Q.
// ---------------------------------------------------------------------------
#define QS_F 2304            // 64*36
#define PS_F 4224            // 128*33
#define OUT_SMEM ((2*QS_F + 2*PS_F) * 4)   // 52224 bytes

__global__ __launch_bounds__(256, 1) void out_mma_kernel(float* __restrict__ out)
{
    extern __shared__ float sm2[];
    float* Qh_s = sm2;                 // [64][36] hi
    float* Ql_s = sm2 + QS_F;          // [64][36] lo
    float* Ph_s = sm2 + 2 * QS_F;      // [128 s][33 t] hi
    float* Pl_s = sm2 + 2 * QS_F + PS_F;

    const int tid = threadIdx.x;
    const int wid = tid >> 5;
    const int lane = tid & 31;
    const int lq = lane >> 2, lr = lane & 3;
    const int bh = blockIdx.z, b = bh >> 4, h = bh & 15;
    const int s0 = blockIdx.x * 128;
    const int m0 = (wid >> 2) * 32;    // 0 or 32
    const int n0 = (wid & 3) * 32;     // 0,32,64,96

    const size_t base = (size_t)b * TT * DD + (size_t)(h * DH) * DD;
    const float* Qg   = g_Q + base;
    const float* Ag   = g_A + (size_t)bh * TT * TT;
    const float* mxp  = g_mx + (size_t)bh * TT;
    const float* invp = g_invs + (size_t)bh * TT;

    // per-thread staging indices
    const int qr0 = tid >> 3;            // 0..31  (Q rows, i adds 32)
    const int qo  = (tid & 7) * 4;       // 0..28  (t within chunk)
    const int ar0 = tid >> 6;            // 0..3   (A rows, i adds 4... see below)

    float acc[2][4][4];
    #pragma unroll
    for (int mt = 0; mt < 2; mt++)
        #pragma unroll
        for (int nt = 0; nt < 4; nt++)
            #pragma unroll
            for (int r = 0; r < 4; r++)
                acc[mt][nt][r] = 0.f;

    float4 qv[2], av[4], iv4;
    float mval[4];

    auto ldg_chunk = [&](int kc) {
        const int k0 = kc * 32;
        iv4 = *reinterpret_cast<const float4*>(&invp[k0 + qo]);
        #pragma unroll
        for (int i = 0; i < 2; i++) {
            const int qr = qr0 + i * 32;
            qv[i] = *reinterpret_cast<const float4*>(&Qg[(size_t)qr * DD + k0 + qo]);
        }
        #pragma unroll
        for (int i = 0; i < 4; i++) {
            const int f = i * 256 + tid;       // 0..1023
            const int ar = f >> 5;             // 0..31 (t row)
            const int ac4 = (f & 31) * 4;      // 0..124 (s col)
            av[i] = *reinterpret_cast<const float4*>(&Ag[(size_t)(k0 + ar) * TT + s0 + ac4]);
            mval[i] = mxp[k0 + ar];
        }
    };

    ldg_chunk(0);
    for (int kc = 0; kc < 32; kc++) {
        if (kc) __syncthreads();
        // stage Q*inv, hi/lo (float4-aligned rows, pad 36)
        #pragma unroll
        for (int i = 0; i < 2; i++) {
            const int qr = qr0 + i * 32;
            float v0 = qv[i].x * iv4.x, v1 = qv[i].y * iv4.y;
            float v2 = qv[i].z * iv4.z, v3 = qv[i].w * iv4.w;
            float h0 = to_tf32(v0), h1 = to_tf32(v1), h2 = to_tf32(v2), h3 = to_tf32(v3);
            *reinterpret_cast<float4*>(&Qh_s[qr * 36 + qo]) = make_float4(h0, h1, h2, h3);
            *reinterpret_cast<float4*>(&Ql_s[qr * 36 + qo]) =
                make_float4(to_tf32(v0 - h0), to_tf32(v1 - h1), to_tf32(v2 - h2), to_tf32(v3 - h3));
        }
        // stage P = exp(A - m), hi/lo, transposed [s][t] pad 33
        #pragma unroll
        for (int i = 0; i < 4; i++) {
            const int f = i * 256 + tid;
            const int ar = f >> 5;
            const int ac4 = (f & 31) * 4;
            const float m = mval[i];
            float e0 = __expf(av[i].x - m), e1 = __expf(av[i].y - m);
            float e2 = __expf(av[i].z - m), e3 = __expf(av[i].w - m);
            float h0 = to_tf32(e0), h1 = to_tf32(e1), h2 = to_tf32(e2), h3 = to_tf32(e3);
            Ph_s[(ac4 + 0) * 33 + ar] = h0;
            Ph_s[(ac4 + 1) * 33 + ar] = h1;
            Ph_s[(ac4 + 2) * 33 + ar] = h2;
            Ph_s[(ac4 + 3) * 33 + ar] = h3;
            Pl_s[(ac4 + 0) * 33 + ar] = to_tf32(e0 - h0);
            Pl_s[(ac4 + 1) * 33 + ar] = to_tf32(e1 - h1);
            Pl_s[(ac4 + 2) * 33 + ar] = to_tf32(e2 - h2);
            Pl_s[(ac4 + 3) * 33 + ar] = to_tf32(e3 - h3);
        }
        __syncthreads();
        if (kc + 1 < 32) ldg_chunk(kc + 1);

        #pragma unroll
        for (int s = 0; s < 4; s++) {
            const int k = s * 8;
            uint32_t ah[2][4], al[2][4];
            #pragma unroll
            for (int mt = 0; mt < 2; mt++) {
                const int r = m0 + mt * 16 + lq;
                ah[mt][0] = __float_as_uint(Qh_s[r * 36 + k + lr]);
                ah[mt][1] = __float_as_uint(Qh_s[(r + 8) * 36 + k + lr]);
                ah[mt][2] = __float_as_uint(Qh_s[r * 36 + k + 4 + lr]);
                ah[mt][3] = __float_as_uint(Qh_s[(r + 8) * 36 + k + 4 + lr]);
                al[mt][0] = __float_as_uint(Ql_s[r * 36 + k + lr]);
                al[mt][1] = __float_as_uint(Ql_s[(r + 8) * 36 + k + lr]);
                al[mt][2] = __float_as_uint(Ql_s[r * 36 + k + 4 + lr]);
                al[mt][3] = __float_as_uint(Ql_s[(r + 8) * 36 + k + 4 + lr]);
            }
            #pragma unroll
            for (int nt = 0; nt < 4; nt++) {
                const int n = n0 + nt * 8 + lq;
                uint32_t bhf[2], blf[2];
                bhf[0] = __float_as_uint(Ph_s[n * 33 + k + lr]);
                bhf[1] = __float_as_uint(Ph_s[n * 33 + k + 4 + lr]);
                blf[0] = __float_as_uint(Pl_s[n * 33 + k + lr]);
                blf[1] = __float_as_uint(Pl_s[n * 33 + k + 4 + lr]);
                MMA_TF32(acc[0][nt], ah[0], bhf);
                MMA_TF32(acc[1][nt], ah[1], bhf);
                MMA_TF32(acc[0][nt], ah[0], blf);
                MMA_TF32(acc[1][nt], ah[1], blf);
                MMA_TF32(acc[0][nt], al[0], bhf);
                MMA_TF32(acc[1][nt], al[1], bhf);
            }
        }
    }

    float* op = out + base;
    #pragma unroll
    for (int mt = 0; mt < 2; mt++) {
        const int rm = m0 + mt * 16 + lq;
        #pragma unroll
        for (int nt = 0; nt < 4; nt++) {
            const int cn = s0 + n0 + nt * 8 + 2 * lr;
            *reinterpret_cast<float2*>(&op[(size_t)rm * DD + cn]) =
                make_float2(acc[mt][nt][0], acc[mt][nt][1]);
            *reinterpret_cast<float2*>(&op[(size_t)(rm + 8) * DD + cn]) =
                make_float2(acc[mt][nt][2], acc[mt][nt][3]);
        }
    }
}

// ---------------------------------------------------------------------------
extern "C" void kernel_launch(void* const* d_in, const int* in_sizes, int n_in,
                              void* d_out, int out_size)
{
    const float* x    = (const float*)d_in[0];
    const float* Wq   = (const float*)d_in[1];
    const float* bq   = (const float*)d_in[2];
    const float* Wk   = (const float*)d_in[3];
    const float* bk   = (const float*)d_in[4];
    const float* Wv   = (const float*)d_in[5];
    const float* bv   = (const float*)d_in[6];
    const float* temp = (const float*)d_in[7];
    float* out = (float*)d_out;

    static float* Qp = nullptr;
    static float *Kp, *Vp, *Xhi, *Xlo, *Wthi, *Wtlo;
    if (!Qp) {
        cudaGetSymbolAddress((void**)&Qp, g_Q);
        cudaGetSymbolAddress((void**)&Kp, g_K);
        cudaGetSymbolAddress((void**)&Vp, g_V);
        cudaGetSymbolAddress((void**)&Xhi, g_Xhi);
        cudaGetSymbolAddress((void**)&Xlo, g_Xlo);
        cudaGetSymbolAddress((void**)&Wthi, g_Wthi);
        cudaGetSymbolAddress((void**)&Wtlo, g_Wtlo);
        cudaFuncSetAttribute(proj_mma_kernel,
                             cudaFuncAttributeMaxDynamicSharedMemorySize, PROJ_SMEM);
        cudaFuncSetAttribute(attn_kernel,
                             cudaFuncAttributeMaxDynamicSharedMemorySize, 65536);
        cudaFuncSetAttribute(out_mma_kernel,
                             cudaFuncAttributeMaxDynamicSharedMemorySize, OUT_SMEM);
    }

    split_x_kernel<<<BT * DD / 1024, 256>>>(x);
    {
        dim3 tg(32, 32);
        dim3 tb(32, 8);
        wtrans_kernel<<<tg, tb>>>(Wq, 0);
        wtrans_kernel<<<tg, tb>>>(Wk, 1);
        wtrans_kernel<<<tg, tb>>>(Wv, 2);
    }

    dim3 pgrid(DD / 128, BT / 128);   // 8 x 32
    proj_mma_kernel<<<pgrid, 256, PROJ_SMEM>>>(Xhi, Xlo, Wthi + 0 * (size_t)DD * DD, Wtlo + 0 * (size_t)DD * DD, bq, Qp);
    proj_mma_kernel<<<pgrid, 256, PROJ_SMEM>>>(Xhi, Xlo, Wthi + 1 * (size_t)DD * DD, Wtlo + 1 * (size_t)DD * DD, bk, Kp);
    proj_mma_kernel<<<pgrid, 256, PROJ_SMEM>>>(Xhi, Xlo, Wthi + 2 * (size_t)DD * DD, Wtlo + 2 * (size_t)DD * DD, bv, Vp);

    dim3 agrid(TT / 128, TT / 128, BB * HH);  // 8 x 8 x 64
    attn_kernel<<<agrid, 256, 65536>>>(temp);

    rowstat_kernel<<<(BB * HH * TT) / 8, 256>>>();

    dim3 ogrid(TT / 128, 1, BB * HH);         // 8 x 1 x 64
    out_mma_kernel<<<ogrid, 256, OUT_SMEM>>>(out);
}